// round 6
// baseline (speedup 1.0000x reference)
#include <cuda_runtime.h>

// Haar DWT2: input [8, 32, 512, 512] f32 -> output [8, 4, 32, 256, 256] f32.
// Subbands stacked at axis 1: (LL, LH, HL, HH).
//
// Deep tile: each thread processes an 8(row) x 4(col) input block -> 4 output
// rows x 2 pixels per subband. A 128-thread CTA covers a contiguous 16 KB
// input span (8 full 2KB rows) for DRAM row-buffer locality; each warp issues
// 8 independent fully-coalesced 512B loads (MLP=8).

#define H 512
#define W 512
#define H2 256
#define W2 256
#define CCH 32                  // channels
#define PLANE_IN (H * W)        // 262144
#define PLANE_OUT (H2 * W2)     // 65536

__device__ __forceinline__ void haar4(float a, float b, float c, float d,
                                      float& ll, float& lh, float& hl, float& hh)
{
    ll = (a + b + c + d) * 0.5f;
    lh = (a + b - c - d) * 0.5f;
    hl = (a - b + c - d) * 0.5f;
    hh = (a - b - c + d) * 0.5f;
}

__global__ __launch_bounds__(128) void haar_dwt2_kernel(
    const float* __restrict__ in, float* __restrict__ out)
{
    const int i   = threadIdx.x;           // 0..127 : float4-col index
    const int q   = blockIdx.x;            // 0..63  : group of 8 input rows
    const int bc  = blockIdx.y;            // 0..255 : b*32 + c
    const int b   = bc >> 5;
    const int c   = bc & 31;
    const int h2  = 4 * q;                 // first output row of this block

    const float* src = in + (size_t)bc * PLANE_IN + (size_t)(8 * q) * W + 4 * i;
    // 8 independent fully-coalesced streaming loads (MLP=8).
    float4 r[8];
#pragma unroll
    for (int k = 0; k < 8; k++)
        r[k] = __ldcs(reinterpret_cast<const float4*>(src + (size_t)k * W));

    // out layout: [b][s][c][h2][w2] with s in {0:LL,1:LH,2:HL,3:HH}
    const size_t base = ((size_t)(b * 4) * CCH + c) * PLANE_OUT
                        + (size_t)h2 * W2 + 2 * i;
    float* o = out + base;
    const size_t sstride = (size_t)CCH * PLANE_OUT;  // subband group stride

#pragma unroll
    for (int j = 0; j < 4; j++) {          // output row h2+j from input rows 2j,2j+1
        const float4 t0 = r[2 * j];
        const float4 t1 = r[2 * j + 1];
        float2 LL, LH, HL, HH;
        haar4(t0.x, t0.y, t1.x, t1.y, LL.x, LH.x, HL.x, HH.x);
        haar4(t0.z, t0.w, t1.z, t1.w, LL.y, LH.y, HL.y, HH.y);
        float* oj = o + (size_t)j * W2;
        __stcs(reinterpret_cast<float2*>(oj),               LL);
        __stcs(reinterpret_cast<float2*>(oj + sstride),     LH);
        __stcs(reinterpret_cast<float2*>(oj + 2 * sstride), HL);
        __stcs(reinterpret_cast<float2*>(oj + 3 * sstride), HH);
    }
}

extern "C" void kernel_launch(void* const* d_in, const int* in_sizes, int n_in,
                              void* d_out, int out_size)
{
    const float* in = (const float*)d_in[0];
    float* out = (float*)d_out;
    dim3 grid(H / 8, 8 * CCH);   // (64 oct-row groups, 256 b*c planes)
    haar_dwt2_kernel<<<grid, 128>>>(in, out);
}